// round 12
// baseline (speedup 1.0000x reference)
#include <cuda_runtime.h>
#include <cuda_bf16.h>
#include <math.h>

#define D        32
#define HALF     16
#define DP1      33       // D+1
#define RSTRIDE4 16       // float4s per relation row (256 B)
#define MAX_NR   1024
#define MAX_NE   1000000

#define TPB      256

// Per-relation table, one float4 per lane l16=0..15:
//   R4[l16] = (C, S, w1, w2) = (cv*c[l16], cv*s[l16], w[l16], w[l16+16])
__device__ __align__(256) float4 g_relTab[MAX_NR * RSTRIDE4];
// Per-relation boost scalars: (cv*s0, c0, w[0], 0)
__device__ float4 g_boost[MAX_NR];
// Per-entity packed (x0, bias)
__device__ float2 g_sc[MAX_NE];

// ---------------------------------------------------------------------------
// Merged prelude: threads pack entities' (x0,bias) (2 per thread); the first
// NR warps additionally build their relation's table (warp-cooperative).
// ---------------------------------------------------------------------------
__global__ void prelude(const float* __restrict__ ent,
                        const float* __restrict__ bias,
                        const float* __restrict__ boost,
                        const float* __restrict__ rot,
                        const float* __restrict__ trans,
                        int NE, int NR) {
    const unsigned FULL = 0xFFFFFFFFu;
    int tid  = blockIdx.x * blockDim.x + threadIdx.x;
    int lane = threadIdx.x & 31;
    int wid  = tid >> 5;
    int nthr = gridDim.x * blockDim.x;

    int e0 = tid;
    int e1 = tid + nthr;
    if (e0 < NE)
        g_sc[e0] = make_float2(__ldg(ent + e0 * DP1), __ldg(bias + e0));
    if (e1 < NE)
        g_sc[e1] = make_float2(__ldg(ent + e1 * DP1), __ldg(bias + e1));

    if (wid < NR) {
        int r = wid;
        // v = 0.1*trans; vn = sqrt(max(|v|^2,1e-6)); w = sinh(vn)/vn * v
        float v  = 0.1f * trans[r * D + lane];
        float sq = v * v;
        #pragma unroll
        for (int off = 16; off; off >>= 1)
            sq += __shfl_xor_sync(FULL, sq, off);
        float vn  = sqrtf(fmaxf(sq, 1e-6f));
        float cv  = coshf(vn);
        float svn = sinhf(vn) / vn;
        float w   = svn * v;

        float whi = __shfl_down_sync(FULL, w, 16);   // lane<16: w[lane+16]

        float s = 0.0f, c = 0.0f;
        float rv = (lane < HALF) ? rot[r * D + lane] : 0.0f;
        sincosf(rv, &s, &c);

        if (lane < HALF)
            g_relTab[r * RSTRIDE4 + lane] = make_float4(cv * c, cv * s, w, whi);

        if (lane == 0) {
            float rap = fminf(fmaxf(boost[r * D], -2.0f), 2.0f);
            g_boost[r] = make_float4(cv * sinhf(rap), coshf(rap), w, 0.0f);
        }
    }
}

// ---------------------------------------------------------------------------
// Main: 16-lane groups, 2 samples/iter, 16 iters/warp.
// 2-stage software pipeline: while computing iteration it, iteration it+2's
// entity gathers are already in flight (8 outstanding loads/warp).
// ---------------------------------------------------------------------------
__global__ __launch_bounds__(TPB, 5) void score16(
        const int*   __restrict__ heads,
        const int*   __restrict__ rels,
        const int*   __restrict__ tails,
        const float* __restrict__ ent,    // [NE,33]
        float*       __restrict__ out,
        int B) {

    const unsigned FULL = 0xFFFFFFFFu;
    const int lane = threadIdx.x & 31;
    const int wid  = (blockIdx.x * TPB + threadIdx.x) >> 5;
    const int i    = wid * 32 + lane;
    const int ic   = min(i, B - 1);
    const int l16  = lane & 15;
    const int gsel = lane & 16;
    const bool hi8 = (l16 & 8) != 0;

    // Coalesced idx loads; random per-own-sample gathers (hot tables).
    const int hi_v = heads[ic];
    const int ri_v = rels [ic];
    const int ti_v = tails[ic];

    float2 sh = g_sc[hi_v];                 // (h0, bias_h)
    float2 st = g_sc[ti_v];                 // (t0, bias_t)
    float4 b4 = __ldg(&g_boost[ri_v]);      // (cv*s0, c0, w0, 0)
    const float bsum   = sh.y + st.y;
    const float t0_own = st.x;
    const float c0_own = b4.y;
    const float bterm  = fmaf(b4.x, sh.x, b4.z);   // cv*s0*h0 + w[0]

    float kss2 = 0.0f, kdt = 0.0f;

    // Pipeline registers: stage 0 (current) and stage 1 (next).
    int   rs0, rs1;
    float a0, b0, ta0, tb0, bts0, c0s0;
    float a1, b1, ta1, tb1, bts1, c0s1;

    // ---- Prologue: fetch iterations 0 and 1 ----
    {
        int src = gsel;                       // it = 0
        int hs = __shfl_sync(FULL, hi_v, src);
        int ts = __shfl_sync(FULL, ti_v, src);
        rs0    = __shfl_sync(FULL, ri_v, src);
        bts0   = __shfl_sync(FULL, bterm,  src);
        c0s0   = __shfl_sync(FULL, c0_own, src);
        const float* hr = ent + hs * DP1;
        const float* tr = ent + ts * DP1;
        a0  = __ldcg(hr + 1  + l16);
        b0  = __ldcg(hr + 17 + l16);
        ta0 = __ldcg(tr + 1  + l16);
        tb0 = __ldcg(tr + 17 + l16);
    }
    {
        int src = gsel | 1;                   // it = 1
        int hs = __shfl_sync(FULL, hi_v, src);
        int ts = __shfl_sync(FULL, ti_v, src);
        rs1    = __shfl_sync(FULL, ri_v, src);
        bts1   = __shfl_sync(FULL, bterm,  src);
        c0s1   = __shfl_sync(FULL, c0_own, src);
        const float* hr = ent + hs * DP1;
        const float* tr = ent + ts * DP1;
        a1  = __ldcg(hr + 1  + l16);
        b1  = __ldcg(hr + 17 + l16);
        ta1 = __ldcg(tr + 1  + l16);
        tb1 = __ldcg(tr + 17 + l16);
    }

    #pragma unroll
    for (int it = 0; it < 16; ++it) {
        // ---- Prefetch iteration it+2 ----
        int   rs_n = 0;
        float a_n = 0.f, b_n = 0.f, ta_n = 0.f, tb_n = 0.f, bts_n = 0.f, c0s_n = 0.f;
        if (it < 14) {
            const int src = gsel | (it + 2);
            int hs = __shfl_sync(FULL, hi_v, src);
            int ts = __shfl_sync(FULL, ti_v, src);
            rs_n   = __shfl_sync(FULL, ri_v, src);
            bts_n  = __shfl_sync(FULL, bterm,  src);
            c0s_n  = __shfl_sync(FULL, c0_own, src);
            const float* hr = ent + hs * DP1;
            const float* tr = ent + ts * DP1;
            a_n  = __ldcg(hr + 1  + l16);
            b_n  = __ldcg(hr + 17 + l16);
            ta_n = __ldcg(tr + 1  + l16);
            tb_n = __ldcg(tr + 17 + l16);
        }

        // ---- Compute iteration it (stage 0 registers) ----
        float4 cw = __ldg(&g_relTab[rs0 * RSTRIDE4 + l16]);   // (C,S,w1,w2) L1-hot

        float r1   = cw.x * a0 - cw.y * b0;                   // cv * rotated[l16]
        float res1 = (l16 == 0) ? fmaf(c0s0, r1, bts0)        // boost + trans dim0
                                : (r1 + cw.z);
        float res2 = fmaf(cw.y, a0, fmaf(cw.x, b0, cw.w));    // cv*rot[l16+16]+w2

        float ss2 = fmaf(res1, res1, res2 * res2);
        float dt  = fmaf(res1, ta0, res2 * tb0);

        // 6-shfl dual reduction within each 16-lane half.
        float u = ss2 + __shfl_xor_sync(FULL, ss2, 8);
        float v = dt  + __shfl_xor_sync(FULL, dt,  8);
        float z = hi8 ? v : u;
        #pragma unroll
        for (int off = 1; off < 8; off <<= 1)
            z += __shfl_xor_sync(FULL, z, off);
        float zz = __shfl_xor_sync(FULL, z, 8);
        float ss2_tot = hi8 ? zz : z;
        float dt_tot  = hi8 ? z  : zz;

        bool keep = (l16 == it);            // lane (gsel|it) owns sample (gsel|it)
        kss2 = keep ? ss2_tot : kss2;
        kdt  = keep ? dt_tot  : kdt;

        // ---- Rotate pipeline: 1 -> 0, new -> 1 ----
        a0 = a1;  b0 = b1;  ta0 = ta1;  tb0 = tb1;  rs0 = rs1;  bts0 = bts1;  c0s0 = c0s1;
        a1 = a_n; b1 = b_n; ta1 = ta_n; tb1 = tb_n; rs1 = rs_n; bts1 = bts_n; c0s1 = c0s_n;
    }

    // Epilogue once per lane on its own sample.
    float ht0   = sqrtf(1.0f + kss2);       // _project time component
    float inner = kdt - ht0 * t0_own;
    float icl   = fmaxf(-inner, 1.0f + 1e-6f);
    float dd    = acoshf(icl);
    if (i < B)
        out[i] = fmaf(-dd, dd, bsum);       // coalesced store
}

// ---------------------------------------------------------------------------
extern "C" void kernel_launch(void* const* d_in, const int* in_sizes, int n_in,
                              void* d_out, int out_size) {
    const int*   heads = (const int*)  d_in[0];
    const int*   rels  = (const int*)  d_in[1];
    const int*   tails = (const int*)  d_in[2];
    const float* ent   = (const float*)d_in[3];
    const float* bw    = (const float*)d_in[4];
    const float* rw    = (const float*)d_in[5];
    const float* tw    = (const float*)d_in[6];
    const float* bias  = (const float*)d_in[7];
    float* out = (float*)d_out;

    int B  = in_sizes[0];
    int NR = in_sizes[4] / D;
    int NE = in_sizes[3] / DP1;

    int pthreads = (NE + 1) / 2;
    int pgrid = (pthreads + TPB - 1) / TPB;
    int minw  = (NR * 32 + TPB - 1) / TPB;
    if (pgrid < minw) pgrid = minw;
    prelude<<<pgrid, TPB>>>(ent, bias, bw, rw, tw, NE, NR);

    int nwarps = (B + 31) / 32;
    int grid   = (nwarps * 32 + TPB - 1) / TPB;
    score16<<<grid, TPB>>>(heads, rels, tails, ent, out, B);
}

// round 13
// speedup vs baseline: 1.1612x; 1.1612x over previous
#include <cuda_runtime.h>
#include <cuda_bf16.h>
#include <math.h>

#define D        32
#define HALF     16
#define DP1      33       // D+1
#define RSTRIDE4 16       // float4s per relation row (256 B)
#define MAX_NR   1024

#define TPB      256

// Per-relation table, one float4 per lane l16=0..15:
//   R4[l16] = (C, S, w1, w2) = (cv*c[l16], cv*s[l16], w[l16], w[l16+16])
__device__ __align__(256) float4 g_relTab[MAX_NR * RSTRIDE4];
// Per-relation boost scalars: (cv*s0, c0, w[0], 0)
__device__ float4 g_boost[MAX_NR];

// ---------------------------------------------------------------------------
// Prelude: relation table only (1000 warps, ~2-3 us). No entity pass.
// ---------------------------------------------------------------------------
__global__ void build_rel_tab(const float* __restrict__ boost,
                              const float* __restrict__ rot,
                              const float* __restrict__ trans,
                              int NR) {
    const unsigned FULL = 0xFFFFFFFFu;
    int lane = threadIdx.x & 31;
    int r = (blockIdx.x * blockDim.x + threadIdx.x) >> 5;
    if (r >= NR) return;

    // v = 0.1*trans; vn = sqrt(max(|v|^2,1e-6)); w = sinh(vn)/vn * v
    float v  = 0.1f * trans[r * D + lane];
    float sq = v * v;
    #pragma unroll
    for (int off = 16; off; off >>= 1)
        sq += __shfl_xor_sync(FULL, sq, off);
    float vn  = sqrtf(fmaxf(sq, 1e-6f));
    float cv  = coshf(vn);
    float svn = sinhf(vn) / vn;
    float w   = svn * v;

    float whi = __shfl_down_sync(FULL, w, 16);   // lane<16: w[lane+16]

    float s = 0.0f, c = 0.0f;
    float rv = (lane < HALF) ? rot[r * D + lane] : 0.0f;
    sincosf(rv, &s, &c);

    if (lane < HALF)
        g_relTab[r * RSTRIDE4 + lane] = make_float4(cv * c, cv * s, w, whi);

    if (lane == 0) {
        float rap = fminf(fmaxf(boost[r * D], -2.0f), 2.0f);
        g_boost[r] = make_float4(cv * sinhf(rap), coshf(rap), w, 0.0f);
    }
}

// ---------------------------------------------------------------------------
// Main: 16-lane groups, 2 samples/iter, 16 iters/warp, 1-stage software
// pipeline (R11 structure). x0/bias loaded directly (x0's sector is already
// fetched by the row gather -> no extra DRAM). (head,rel) packed into one
// int so each iteration needs one fewer index shuffle.
// ---------------------------------------------------------------------------
__global__ __launch_bounds__(TPB, 6) void score16(
        const int*   __restrict__ heads,
        const int*   __restrict__ rels,
        const int*   __restrict__ tails,
        const float* __restrict__ ent,    // [NE,33]
        const float* __restrict__ bias,   // [NE,1]
        float*       __restrict__ out,
        int B) {

    const unsigned FULL = 0xFFFFFFFFu;
    const int lane = threadIdx.x & 31;
    const int wid  = (blockIdx.x * TPB + threadIdx.x) >> 5;
    const int i    = wid * 32 + lane;
    const int ic   = min(i, B - 1);
    const int l16  = lane & 15;
    const int gsel = lane & 16;
    const bool hi8 = (l16 & 8) != 0;

    // Coalesced idx loads; direct random scalar gathers for own sample.
    const int hi_v = heads[ic];
    const int ri_v = rels [ic];
    const int ti_v = tails[ic];
    const int pk_v = (hi_v << 10) | ri_v;     // head(<=2^20) | rel(<1024)

    const float h0_own = __ldcg(ent + hi_v * DP1);   // sector shared w/ a-load
    const float t0_own = __ldcg(ent + ti_v * DP1);
    const float bsum   = __ldg(bias + hi_v) + __ldg(bias + ti_v);

    float4 b4 = __ldg(&g_boost[ri_v]);        // (cv*s0, c0, w0, 0)
    const float c0_own = b4.y;
    const float bterm  = fmaf(b4.x, h0_own, b4.z);   // cv*s0*h0 + w[0]

    float kss2 = 0.0f, kdt = 0.0f;

    // ---- Pipeline prologue: fetch iteration 0 ----
    int   rs_c, hs_c;
    float a_c, b_c, ta_c, tb_c, bts_c, c0s_c;
    {
        int src = gsel;
        int pc  = __shfl_sync(FULL, pk_v, src);
        int ts  = __shfl_sync(FULL, ti_v, src);
        bts_c   = __shfl_sync(FULL, bterm,  src);
        c0s_c   = __shfl_sync(FULL, c0_own, src);
        hs_c = pc >> 10;
        rs_c = pc & 1023;
        const float* hr = ent + hs_c * DP1;
        const float* tr = ent + ts * DP1;
        a_c  = __ldcg(hr + 1  + l16);
        b_c  = __ldcg(hr + 17 + l16);
        ta_c = __ldcg(tr + 1  + l16);
        tb_c = __ldcg(tr + 17 + l16);
    }

    #pragma unroll
    for (int it = 0; it < 16; ++it) {
        // ---- Prefetch iteration it+1 (overlaps reduction below) ----
        int   rs_n = 0;
        float a_n = 0.f, b_n = 0.f, ta_n = 0.f, tb_n = 0.f, bts_n = 0.f, c0s_n = 0.f;
        if (it < 15) {
            const int src = gsel | (it + 1);
            int pc = __shfl_sync(FULL, pk_v, src);
            int ts = __shfl_sync(FULL, ti_v, src);
            bts_n  = __shfl_sync(FULL, bterm,  src);
            c0s_n  = __shfl_sync(FULL, c0_own, src);
            int hs = pc >> 10;
            rs_n   = pc & 1023;
            const float* hr = ent + hs * DP1;
            const float* tr = ent + ts * DP1;
            a_n  = __ldcg(hr + 1  + l16);
            b_n  = __ldcg(hr + 17 + l16);
            ta_n = __ldcg(tr + 1  + l16);
            tb_n = __ldcg(tr + 17 + l16);
        }

        // ---- Compute iteration it ----
        float4 cw = __ldg(&g_relTab[rs_c * RSTRIDE4 + l16]);  // (C,S,w1,w2) L1-hot

        float r1   = cw.x * a_c - cw.y * b_c;                 // cv * rotated[l16]
        float res1 = (l16 == 0) ? fmaf(c0s_c, r1, bts_c)      // boost + trans dim0
                                : (r1 + cw.z);
        float res2 = fmaf(cw.y, a_c, fmaf(cw.x, b_c, cw.w));  // cv*rot[l16+16]+w2

        float ss2 = fmaf(res1, res1, res2 * res2);
        float dt  = fmaf(res1, ta_c, res2 * tb_c);

        // 6-shfl dual reduction within each 16-lane half.
        float u = ss2 + __shfl_xor_sync(FULL, ss2, 8);
        float v = dt  + __shfl_xor_sync(FULL, dt,  8);
        float z = hi8 ? v : u;
        #pragma unroll
        for (int off = 1; off < 8; off <<= 1)
            z += __shfl_xor_sync(FULL, z, off);
        float zz = __shfl_xor_sync(FULL, z, 8);
        float ss2_tot = hi8 ? zz : z;
        float dt_tot  = hi8 ? z  : zz;

        bool keep = (l16 == it);            // lane (gsel|it) owns sample (gsel|it)
        kss2 = keep ? ss2_tot : kss2;
        kdt  = keep ? dt_tot  : kdt;

        // ---- Rotate pipeline registers ----
        a_c = a_n; b_c = b_n; ta_c = ta_n; tb_c = tb_n;
        rs_c = rs_n; bts_c = bts_n; c0s_c = c0s_n;
    }

    // Epilogue once per lane on its own sample.
    float ht0   = sqrtf(1.0f + kss2);       // _project time component
    float inner = kdt - ht0 * t0_own;
    float icl   = fmaxf(-inner, 1.0f + 1e-6f);
    float dd    = acoshf(icl);
    if (i < B)
        out[i] = fmaf(-dd, dd, bsum);       // coalesced store
}

// ---------------------------------------------------------------------------
extern "C" void kernel_launch(void* const* d_in, const int* in_sizes, int n_in,
                              void* d_out, int out_size) {
    const int*   heads = (const int*)  d_in[0];
    const int*   rels  = (const int*)  d_in[1];
    const int*   tails = (const int*)  d_in[2];
    const float* ent   = (const float*)d_in[3];
    const float* bw    = (const float*)d_in[4];
    const float* rw    = (const float*)d_in[5];
    const float* tw    = (const float*)d_in[6];
    const float* bias  = (const float*)d_in[7];
    float* out = (float*)d_out;

    int B  = in_sizes[0];
    int NR = in_sizes[4] / D;

    build_rel_tab<<<(NR * 32 + TPB - 1) / TPB, TPB>>>(bw, rw, tw, NR);

    int nwarps = (B + 31) / 32;
    int grid   = (nwarps * 32 + TPB - 1) / TPB;
    score16<<<grid, TPB>>>(heads, rels, tails, ent, bias, out, B);
}

// round 14
// speedup vs baseline: 1.2016x; 1.0347x over previous
#include <cuda_runtime.h>
#include <cuda_bf16.h>
#include <math.h>

#define D        32
#define HALF     16
#define DP1      33       // D+1
#define RSTRIDE4 16       // float4s per relation row (256 B)
#define MAX_NR   1024

#define TPB      256

// Per-relation table, one float4 per slot j=0..15:
//   R4[j] = (C, S, w1, w2) = (cv*c[j], cv*s[j], w[j], w[j+16])
__device__ __align__(256) float4 g_relTab[MAX_NR * RSTRIDE4];
// Per-relation boost scalars: (cv*s0, c0, w[0], 0)
__device__ float4 g_boost[MAX_NR];

// ---------------------------------------------------------------------------
// Prelude: relation table only (1000 warps, ~2-3 us). No entity pass.
// ---------------------------------------------------------------------------
__global__ void build_rel_tab(const float* __restrict__ boost,
                              const float* __restrict__ rot,
                              const float* __restrict__ trans,
                              int NR) {
    const unsigned FULL = 0xFFFFFFFFu;
    int lane = threadIdx.x & 31;
    int r = (blockIdx.x * blockDim.x + threadIdx.x) >> 5;
    if (r >= NR) return;

    // v = 0.1*trans; vn = sqrt(max(|v|^2,1e-6)); w = sinh(vn)/vn * v
    float v  = 0.1f * trans[r * D + lane];
    float sq = v * v;
    #pragma unroll
    for (int off = 16; off; off >>= 1)
        sq += __shfl_xor_sync(FULL, sq, off);
    float vn  = sqrtf(fmaxf(sq, 1e-6f));
    float cv  = coshf(vn);
    float svn = sinhf(vn) / vn;
    float w   = svn * v;

    float whi = __shfl_down_sync(FULL, w, 16);   // lane<16: w[lane+16]

    float s = 0.0f, c = 0.0f;
    float rv = (lane < HALF) ? rot[r * D + lane] : 0.0f;
    sincosf(rv, &s, &c);

    if (lane < HALF)
        g_relTab[r * RSTRIDE4 + lane] = make_float4(cv * c, cv * s, w, whi);

    if (lane == 0) {
        float rap = fminf(fmaxf(boost[r * D], -2.0f), 2.0f);
        g_boost[r] = make_float4(cv * sinhf(rap), coshf(rap), w, 0.0f);
    }
}

// ---------------------------------------------------------------------------
// Main: 16-lane groups, 2 samples/iter, 16 iters/warp, 1-stage pipeline.
// Rotated dimension ownership: at iteration it, lane l16 handles dims
// ((l16-it)&15, +16). Dim 0 thus lands on the sample's OWN lane (l16==it),
// so the boost uses the lane's own scalars — no bts/c0s shuffles at all.
// ---------------------------------------------------------------------------
__global__ __launch_bounds__(TPB, 6) void score16(
        const int*   __restrict__ heads,
        const int*   __restrict__ rels,
        const int*   __restrict__ tails,
        const float* __restrict__ ent,    // [NE,33]
        const float* __restrict__ bias,   // [NE,1]
        float*       __restrict__ out,
        int B) {

    const unsigned FULL = 0xFFFFFFFFu;
    const int lane = threadIdx.x & 31;
    const int wid  = (blockIdx.x * TPB + threadIdx.x) >> 5;
    const int i    = wid * 32 + lane;
    const int ic   = min(i, B - 1);
    const int l16  = lane & 15;
    const int gsel = lane & 16;
    const bool hi8 = (l16 & 8) != 0;

    // Coalesced idx loads; direct random scalar gathers for own sample.
    const int hi_v = heads[ic];
    const int ri_v = rels [ic];
    const int ti_v = tails[ic];
    const int pk_v = (hi_v << 10) | ri_v;     // head(<2^20) | rel(<1024)

    const float h0_own = __ldcg(ent + hi_v * DP1);   // sector shared w/ a-load
    const float t0_own = __ldcg(ent + ti_v * DP1);
    const float bsum   = __ldg(bias + hi_v) + __ldg(bias + ti_v);

    float4 b4 = __ldg(&g_boost[ri_v]);        // (cv*s0, c0, w0, 0)
    const float c0_own = b4.y;
    const float bterm  = fmaf(b4.x, h0_own, b4.z);   // cv*s0*h0 + w[0]

    float kss2 = 0.0f, kdt = 0.0f;

    // ---- Pipeline prologue: fetch iteration 0 (j = l16) ----
    int   rs_c;
    float a_c, b_c, ta_c, tb_c;
    {
        int src = gsel;
        int pc  = __shfl_sync(FULL, pk_v, src);
        int ts  = __shfl_sync(FULL, ti_v, src);
        int hs  = pc >> 10;
        rs_c    = pc & 1023;
        const float* hr = ent + hs * DP1;
        const float* tr = ent + ts * DP1;
        a_c  = __ldcg(hr + 1  + l16);
        b_c  = __ldcg(hr + 17 + l16);
        ta_c = __ldcg(tr + 1  + l16);
        tb_c = __ldcg(tr + 17 + l16);
    }

    #pragma unroll
    for (int it = 0; it < 16; ++it) {
        const int j_c = (l16 - it) & 15;    // dim handled this iteration

        // ---- Prefetch iteration it+1 (rotated window; same sectors) ----
        int   rs_n = 0;
        float a_n = 0.f, b_n = 0.f, ta_n = 0.f, tb_n = 0.f;
        if (it < 15) {
            const int src = gsel | (it + 1);
            const int j_n = (l16 - (it + 1)) & 15;
            int pc = __shfl_sync(FULL, pk_v, src);
            int ts = __shfl_sync(FULL, ti_v, src);
            int hs = pc >> 10;
            rs_n   = pc & 1023;
            const float* hr = ent + hs * DP1;
            const float* tr = ent + ts * DP1;
            a_n  = __ldcg(hr + 1  + j_n);
            b_n  = __ldcg(hr + 17 + j_n);
            ta_n = __ldcg(tr + 1  + j_n);
            tb_n = __ldcg(tr + 17 + j_n);
        }

        // ---- Compute iteration it ----
        float4 cw = __ldg(&g_relTab[rs_c * RSTRIDE4 + j_c]);  // (C,S,w1,w2) L1-hot

        const bool own = (l16 == it);       // this lane owns sample gsel|it,
                                            // and (rotation) handles dim 0
        float r1   = cw.x * a_c - cw.y * b_c;                 // cv * rotated[j]
        float res1 = own ? fmaf(c0_own, r1, bterm)            // boost + trans dim0
                         : (r1 + cw.z);
        float res2 = fmaf(cw.y, a_c, fmaf(cw.x, b_c, cw.w));  // cv*rot[j+16]+w2

        float ss2 = fmaf(res1, res1, res2 * res2);
        float dt  = fmaf(res1, ta_c, res2 * tb_c);

        // 6-shfl dual reduction within each 16-lane half.
        float u = ss2 + __shfl_xor_sync(FULL, ss2, 8);
        float v = dt  + __shfl_xor_sync(FULL, dt,  8);
        float z = hi8 ? v : u;
        #pragma unroll
        for (int off = 1; off < 8; off <<= 1)
            z += __shfl_xor_sync(FULL, z, off);
        float zz = __shfl_xor_sync(FULL, z, 8);
        float ss2_tot = hi8 ? zz : z;
        float dt_tot  = hi8 ? z  : zz;

        kss2 = own ? ss2_tot : kss2;        // owner lane keeps its sample
        kdt  = own ? dt_tot  : kdt;

        // ---- Rotate pipeline registers ----
        a_c = a_n; b_c = b_n; ta_c = ta_n; tb_c = tb_n; rs_c = rs_n;
    }

    // Epilogue once per lane on its own sample.
    float ht0   = sqrtf(1.0f + kss2);       // _project time component
    float inner = kdt - ht0 * t0_own;
    float icl   = fmaxf(-inner, 1.0f + 1e-6f);
    float dd    = acoshf(icl);
    if (i < B)
        out[i] = fmaf(-dd, dd, bsum);       // coalesced store
}

// ---------------------------------------------------------------------------
extern "C" void kernel_launch(void* const* d_in, const int* in_sizes, int n_in,
                              void* d_out, int out_size) {
    const int*   heads = (const int*)  d_in[0];
    const int*   rels  = (const int*)  d_in[1];
    const int*   tails = (const int*)  d_in[2];
    const float* ent   = (const float*)d_in[3];
    const float* bw    = (const float*)d_in[4];
    const float* rw    = (const float*)d_in[5];
    const float* tw    = (const float*)d_in[6];
    const float* bias  = (const float*)d_in[7];
    float* out = (float*)d_out;

    int B  = in_sizes[0];
    int NR = in_sizes[4] / D;

    build_rel_tab<<<(NR * 32 + TPB - 1) / TPB, TPB>>>(bw, rw, tw, NR);

    int nwarps = (B + 31) / 32;
    int grid   = (nwarps * 32 + TPB - 1) / TPB;
    score16<<<grid, TPB>>>(heads, rels, tails, ent, bias, out, B);
}